// round 14
// baseline (speedup 1.0000x reference)
#include <cuda_runtime.h>
#include <cuda_fp16.h>
#include <cstdint>

// Problem constants (fixed by setup_inputs)
#define Bb 4
#define Ts 4096
#define Dd 2560
#define Hh 10
#define BW 256
#define Mrows (Bb*Ts)   // 16384
#define NCHAN (Bb*Dd)   // 10240

// Scratch
__device__ float2 g_ax[(size_t)Bb * Ts * Dd];    // interleaved (a_eff, x_norm)
__device__ float  g_sp[Dd];                      // softplus(recurrent_param)
// Pre-packed, pre-swizzled fp16 tiles (exact smem layout, bulk-copied):
__device__ __align__(128) char g_aP[(size_t)Mrows * Dd * 2];
__device__ __align__(128) char g_wP[(size_t)Hh * 4 * 4 * 128 * 128];

// chunked-scan partials (chunk = 64 t's, matching the gates CTA tile)
#define CH 64
#define NCH (Ts / CH)    // 64
__device__ float g_P2[NCH * NCHAN];
__device__ float g_h2[NCH * NCHAN];
__device__ float g_H2[NCH * NCHAN];

// ---------------------------------------------------------------------------
__device__ __forceinline__ uint32_t smem_u32(const void* p) {
    uint32_t a;
    asm("{ .reg .u64 t; cvta.to.shared.u64 t, %1; cvt.u32.u64 %0, t; }" : "=r"(a) : "l"(p));
    return a;
}
__device__ __forceinline__ void mma_f16(float* c, const uint32_t* a,
                                        uint32_t b0, uint32_t b1) {
    asm volatile("mma.sync.aligned.m16n8k16.row.col.f32.f16.f16.f32 "
                 "{%0,%1,%2,%3}, {%4,%5,%6,%7}, {%8,%9}, {%0,%1,%2,%3};"
                 : "+f"(c[0]), "+f"(c[1]), "+f"(c[2]), "+f"(c[3])
                 : "r"(a[0]), "r"(a[1]), "r"(a[2]), "r"(a[3]), "r"(b0), "r"(b1));
}
__device__ __forceinline__ void ldm_x4(uint32_t* r, uint32_t addr) {
    asm volatile("ldmatrix.sync.aligned.m8n8.x4.shared.b16 {%0,%1,%2,%3}, [%4];"
                 : "=r"(r[0]), "=r"(r[1]), "=r"(r[2]), "=r"(r[3]) : "r"(addr));
}
#define MBAR_INIT(mbar, cnt) \
    asm volatile("mbarrier.init.shared.b64 [%0], %1;" :: "r"(mbar), "r"(cnt) : "memory")
#define MBAR_EXPECT(mbar, bytes) \
    asm volatile("mbarrier.arrive.expect_tx.shared.b64 _, [%0], %1;" :: "r"(mbar), "r"(bytes) : "memory")
#define MBAR_WAIT(mbar, par) do {                                              \
    uint32_t _m = (mbar), _p = (par), _d;                                      \
    asm volatile("{ .reg .pred p; mbarrier.try_wait.parity.acquire.cta.shared::cta.b64 p, [%1], %2; selp.b32 %0,1,0,p; }" \
                 : "=r"(_d) : "r"(_m), "r"(_p) : "memory");                    \
    if (!_d) {                                                                 \
        asm volatile("{ .reg .pred P1; WL_%=: mbarrier.try_wait.parity.acquire.cta.shared::cta.b64 P1, [%0], %1, 0x989680; @P1 bra.uni WD_%=; bra.uni WL_%=; WD_%=: }" \
                     :: "r"(_m), "r"(_p) : "memory");                          \
    } } while (0)
#define BULK_G2S(dst, src, sz, mbar) \
    asm volatile("cp.async.bulk.shared::cluster.global.mbarrier::complete_tx::bytes [%0], [%1], %2, [%3];" \
                 :: "r"(dst), "l"(src), "r"(sz), "r"(mbar) : "memory")

// ---------------------------------------------------------------------------
// Kernel 0: softplus table
// ---------------------------------------------------------------------------
__global__ void sp_kernel(const float* __restrict__ rp) {
    int d = blockIdx.x * blockDim.x + threadIdx.x;
    if (d < Dd) {
        float x = rp[d];
        g_sp[d] = (x > 20.0f) ? x : log1pf(__expf(x));
    }
}

// ---------------------------------------------------------------------------
// Kernel 0b: pack weights -> g_wP[h][nq][kt][n(128)][128B swizzled], fp16,
// interleaved n = 2*j_local + gate, j = nq*64 + j_local. One thread per 16B.
// ---------------------------------------------------------------------------
__global__ __launch_bounds__(256) void wt_kernel(
    const float* __restrict__ wig, const float* __restrict__ wrg)
{
    int idx = blockIdx.x * 256 + threadIdx.x;   // Hh*4*4*128*8 = 163840
    int ch = idx & 7;
    int n  = (idx >> 3) & 127;
    int kt = (idx >> 10) & 3;
    int nq = (idx >> 12) & 3;
    int h  = idx >> 14;
    int j  = nq * 64 + (n >> 1);
    const float* src = (n & 1) ? wrg : wig;
    src += (size_t)h * BW * BW + j;             // + k*BW
    int kb = kt * 64 + ch * 8;
    __half2 v[4];
    #pragma unroll
    for (int i = 0; i < 4; i++)
        v[i] = __floats2half2_rn(src[(size_t)(kb + 2*i) * BW],
                                 src[(size_t)(kb + 2*i + 1) * BW]);
    size_t dst = ((((size_t)(h * 4 + nq) * 4 + kt) * 128 + n) * 128) + ((ch ^ (n & 7)) * 16);
    *(uint4*)(g_wP + dst) = *(uint4*)v;
}

// ---------------------------------------------------------------------------
// Kernel 0c: pack activations -> g_aP[tile(64r)][h][kt][r(64)][128B swizzled].
// ---------------------------------------------------------------------------
__global__ __launch_bounds__(320) void cvt_kernel(const float* __restrict__ act) {
    int row = blockIdx.x;
    int k   = threadIdx.x * 8;
    int h   = k >> 8;
    int kk  = k & 255;
    int kt  = kk >> 6;
    int ch  = (kk >> 3) & 7;
    int r    = row & 63;
    int tile = row >> 6;
    const float* s = act + (size_t)row * Dd + k;
    float4 v0 = *(const float4*)s;
    float4 v1 = *(const float4*)(s + 4);
    __half2 hv[4];
    hv[0] = __floats2half2_rn(v0.x, v0.y);
    hv[1] = __floats2half2_rn(v0.z, v0.w);
    hv[2] = __floats2half2_rn(v1.x, v1.y);
    hv[3] = __floats2half2_rn(v1.z, v1.w);
    size_t dst = ((((size_t)(tile * Hh + h) * 4 + kt) * 64 + r) * 128) + ((ch ^ (r & 7)) * 16);
    *(uint4*)(g_aP + dst) = *(uint4*)hv;
}

// ---------------------------------------------------------------------------
// Kernel 1: fp16 mma gates GEMM (R10 mainloop). Epilogue: act read from a
// bulk-copied fp16 A slab (kt=nq) in smem; results staged in sm2 once, then
// (i) coalesced uint4 g_ax stores, (ii) fused chunk-scan aggregates.
// ---------------------------------------------------------------------------
#define STG_A 8192
#define STG_W 16384
#define STG_B (STG_A + STG_W)          // 24576
#define SM_ST0 1024
#define SMEM_TOT (SM_ST0 + 2 * STG_B)  // 50176
#define EPI_PITCH 66                   // float2 pitch (2-way bank access)
// sm2 staging region: disjoint from buffer0's A slab [SM_ST0, SM_ST0+8192)
#define SM_EPI (SM_ST0 + STG_A)        // 9216 ; 64*66*8 = 33792 -> ends 43008
#define SM_COMB (SM_EPI + 64 * EPI_PITCH * 8)   // 43008 ; +2048 = 45056 <= 50176

__global__ __launch_bounds__(256, 4) void gates_mma_kernel(
    const int* __restrict__ pos,
    const float* __restrict__ big, const float* __restrict__ brg)
{
    extern __shared__ char smc[];
    const uint32_t sb = smem_u32(smc);

    const int tid = threadIdx.x;
    const int wid = tid >> 5, lane = tid & 31;
    const int g = lane >> 2, t = lane & 3;
    const int wm = wid & 1;
    const int wn = wid >> 1;
    const int h  = blockIdx.z;
    const int nq = blockIdx.y;
    const int tile = blockIdx.x;
    const int rb = tile * 64;

    if (tid == 0) { MBAR_INIT(sb + 0, 1); MBAR_INIT(sb + 8, 1); }
    __syncthreads();

    const char* aSrc = g_aP + ((size_t)(tile * Hh + h) * 4) * STG_A;
    const char* wSrc = g_wP + ((size_t)(h * 4 + nq) * 4) * STG_W;
    if (tid == 0) {
        #pragma unroll
        for (int s = 0; s < 2; s++) {
            uint32_t mb = sb + s * 8;
            uint32_t ds = sb + SM_ST0 + s * STG_B;
            MBAR_EXPECT(mb, STG_B);
            BULK_G2S(ds,         aSrc + (size_t)s * STG_A, STG_A, mb);
            BULK_G2S(ds + STG_A, wSrc + (size_t)s * STG_W, STG_W, mb);
        }
    }

    float acc[2][4][4];
    #pragma unroll
    for (int mt = 0; mt < 2; mt++)
        #pragma unroll
        for (int nt = 0; nt < 4; nt++)
            #pragma unroll
            for (int c = 0; c < 4; c++) acc[mt][nt][c] = 0.0f;

    const int jA    = lane & 7;
    const int hi16A = ((lane >> 4) & 1) << 4;
    const uint32_t rowA0 = (uint32_t)(wm * 32 + ((lane >> 3) & 1) * 8 + jA) * 128;
    const uint32_t rowB  = (uint32_t)(wn * 32 + (lane >> 3) * 8 + jA) * 128;

    #pragma unroll
    for (int kt = 0; kt < 4; kt++) {
        MBAR_WAIT(sb + (kt & 1) * 8, (kt >> 1) & 1);
        const uint32_t Abase = sb + SM_ST0 + (kt & 1) * STG_B;
        const uint32_t Wbase = Abase + STG_A;

        #pragma unroll
        for (int k16 = 0; k16 < 4; k16++) {
            const uint32_t b0 = (uint32_t)(((k16 * 2) ^ jA) << 4);
            uint32_t af0[4], af1[4], blo[4], bhi[4];
            ldm_x4(af0, Abase + rowA0 + (b0 ^ hi16A));
            ldm_x4(af1, Abase + rowA0 + 2048 + (b0 ^ hi16A));
            ldm_x4(blo, Wbase + rowB + b0);
            ldm_x4(bhi, Wbase + rowB + (b0 ^ 16));
            #pragma unroll
            for (int nt = 0; nt < 4; nt++) {
                mma_f16(acc[0][nt], af0, blo[nt], bhi[nt]);
                mma_f16(acc[1][nt], af1, blo[nt], bhi[nt]);
            }
        }
        if (kt < 2) {
            __syncthreads();
            if (tid == 0) {
                uint32_t mb = sb + (kt & 1) * 8;
                uint32_t ds = sb + SM_ST0 + (kt & 1) * STG_B;
                MBAR_EXPECT(mb, STG_B);
                BULK_G2S(ds,         aSrc + (size_t)(kt + 2) * STG_A, STG_A, mb);
                BULK_G2S(ds + STG_A, wSrc + (size_t)(kt + 2) * STG_W, STG_W, mb);
            }
        } else if (kt == 2) {
            // buffer0's A region is now dead: DMA the epilogue act slab
            // (kt = nq) into it. 3rd phase on mbar0 -> wait parity 0.
            __syncthreads();
            if (tid == 0) {
                MBAR_EXPECT(sb + 0, STG_A);
                BULK_G2S(sb + SM_ST0, aSrc + (size_t)nq * STG_A, STG_A, sb + 0);
            }
        }
    }

    // mainloop compute done; sm2 staging overlaps buffer1 -> sync first
    __syncthreads();
    MBAR_WAIT(sb + 0, 0);          // epilogue act slab landed

    // -------- fused epilogue: gate math -> sm2 stage --------
    float bi[4], br[4], sp4[4];
    const int dg0 = h * BW + nq * 64 + wn * 16 + t;
    #pragma unroll
    for (int nt = 0; nt < 4; nt++) {
        int dg = dg0 + nt * 4;
        bi[nt]  = big[dg];
        br[nt]  = brg[dg];
        sp4[nt] = g_sp[dg];
    }

    float2* sm2 = (float2*)(smc + SM_EPI);   // [64 rows][pitch 66]
    const char* Ae = smc + SM_ST0;           // fp16 act slab (kt = nq), swizzled

    #pragma unroll
    for (int mt = 0; mt < 2; mt++) {
        int lr1 = wm * 32 + mt * 16 + g;
        int lr2 = lr1 + 8;
        int r1 = rb + lr1, r2 = rb + lr2;
        bool rs1 = (pos[r1] == 0);
        bool rs2 = (pos[r2] == 0);
        #pragma unroll
        for (int nt = 0; nt < 4; nt++) {
            int kk  = wn * 16 + nt * 4 + t;      // local channel == local k
            float av1 = __half2float(*(const __half*)(Ae + lr1 * 128 +
                            ((((kk >> 3) ^ (lr1 & 7)) << 4) | ((kk & 7) << 1))));
            float av2 = __half2float(*(const __half*)(Ae + lr2 * 128 +
                            ((((kk >> 3) ^ (lr2 & 7)) << 4) | ((kk & 7) << 1))));
            {
                float ig = 1.0f / (1.0f + __expf(-(acc[mt][nt][0] + bi[nt])));
                float rg = 1.0f / (1.0f + __expf(-(acc[mt][nt][1] + br[nt])));
                float a  = __expf(-8.0f * rg * sp4[nt]);
                float m  = sqrtf(fmaxf(fmaf(-a, a, 1.0f), 0.0f));
                sm2[lr1 * EPI_PITCH + kk] =
                    make_float2(rs1 ? 0.0f : a, av1 * ig * (rs1 ? 1.0f : m));
            }
            {
                float ig = 1.0f / (1.0f + __expf(-(acc[mt][nt][2] + bi[nt])));
                float rg = 1.0f / (1.0f + __expf(-(acc[mt][nt][3] + br[nt])));
                float a  = __expf(-8.0f * rg * sp4[nt]);
                float m  = sqrtf(fmaxf(fmaf(-a, a, 1.0f), 0.0f));
                sm2[lr2 * EPI_PITCH + kk] =
                    make_float2(rs2 ? 0.0f : a, av2 * ig * (rs2 ? 1.0f : m));
            }
        }
    }
    __syncthreads();

    // -------- coalesced g_ax stores (warp = one 512B row) --------
    float2* gdst = g_ax + (size_t)rb * Dd + h * BW + nq * 64;
    #pragma unroll
    for (int i = 0; i < 8; i++) {
        int idx = i * 256 + tid;
        int r = idx >> 5, q = idx & 31;
        uint4 v = *(uint4*)&sm2[r * EPI_PITCH + q * 2];
        *(uint4*)(gdst + (size_t)r * Dd + q * 2) = v;
    }

    // -------- fused chunk-scan aggregates (chunk = this tile's 64 t's) -----
    {
        int chl = tid & 63, seg = tid >> 6;      // 4 segments x 16 t
        float P = 1.0f, hh = 0.0f;
        #pragma unroll
        for (int i = 0; i < 16; i++) {
            float2 v = sm2[(seg * 16 + i) * EPI_PITCH + chl];
            P *= v.x;
            hh = fmaf(v.x, hh, v.y);
        }
        float2* comb = (float2*)(smc + SM_COMB);
        comb[seg * 64 + chl] = make_float2(P, hh);
        __syncthreads();
        if (tid < 64) {
            float Pt = 1.0f, ht = 0.0f;
            #pragma unroll
            for (int s = 0; s < 4; s++) {
                float2 v = comb[s * 64 + tid];
                ht = fmaf(v.x, ht, v.y);
                Pt *= v.x;
            }
            int bb = tile >> 6, cc = tile & 63;
            int chan = bb * Dd + h * BW + nq * 64 + tid;
            g_P2[cc * NCHAN + chan] = Pt;
            g_h2[cc * NCHAN + chan] = ht;
        }
    }
}

// ---------------------------------------------------------------------------
// Kernel 2b: cross-chunk recurrence (64 steps per channel)
// ---------------------------------------------------------------------------
__global__ __launch_bounds__(128) void scan_link_kernel() {
    int ch = blockIdx.x * 128 + threadIdx.x;
    float H = 0.0f;
    #pragma unroll
    for (int c = 0; c < NCH; c++) {
        g_H2[c * NCHAN + ch] = H;
        H = fmaf(g_P2[c * NCHAN + ch], H, g_h2[c * NCHAN + ch]);
    }
}

// ---------------------------------------------------------------------------
// Kernel 2c: seeded local scan, write output. grid (80, 64).
// ---------------------------------------------------------------------------
__global__ __launch_bounds__(128) void scan_final_kernel(float* __restrict__ out) {
    int ch = blockIdx.x * 128 + threadIdx.x;
    int c  = blockIdx.y;
    int b  = ch / Dd;
    int d  = ch - b * Dd;
    size_t base = (size_t)b * Ts * Dd + (size_t)c * CH * Dd + d;

    float hacc = g_H2[c * NCHAN + ch];
    #pragma unroll 1
    for (int t0 = 0; t0 < CH; t0 += 8) {
        float2 v[8];
        #pragma unroll
        for (int u = 0; u < 8; u++) v[u] = g_ax[base + (size_t)(t0 + u) * Dd];
        #pragma unroll
        for (int u = 0; u < 8; u++) {
            hacc = fmaf(v[u].x, hacc, v[u].y);
            out[base + (size_t)(t0 + u) * Dd] = hacc;
        }
    }
}

// ---------------------------------------------------------------------------
extern "C" void kernel_launch(void* const* d_in, const int* in_sizes, int n_in,
                              void* d_out, int out_size) {
    const float* act = (const float*)d_in[0];
    const int*   pos = (const int*)  d_in[1];
    const float* wig = (const float*)d_in[2];
    const float* big = (const float*)d_in[3];
    const float* wrg = (const float*)d_in[4];
    const float* brg = (const float*)d_in[5];
    const float* rp  = (const float*)d_in[6];
    float* out = (float*)d_out;

    static int smem_set = 0;
    if (!smem_set) {
        cudaFuncSetAttribute(gates_mma_kernel,
                             cudaFuncAttributeMaxDynamicSharedMemorySize, SMEM_TOT);
        smem_set = 1;
    }

    sp_kernel<<<(Dd + 255) / 256, 256>>>(rp);
    wt_kernel<<<(Hh * 4 * 4 * 128 * 8) / 256, 256>>>(wig, wrg);
    cvt_kernel<<<Mrows, 320>>>(act);

    dim3 grid(Mrows / 64, 4, Hh);    // (256, 4, 10) = 10240 CTAs
    gates_mma_kernel<<<grid, 256, SMEM_TOT>>>(pos, big, brg);

    scan_link_kernel<<<NCHAN / 128, 128>>>();
    dim3 sgrid(NCHAN / 128, NCH);    // (80, 64)
    scan_final_kernel<<<sgrid, 128>>>(out);
}

// round 15
// speedup vs baseline: 1.0297x; 1.0297x over previous
#include <cuda_runtime.h>
#include <cuda_fp16.h>
#include <cstdint>

// Problem constants (fixed by setup_inputs)
#define Bb 4
#define Ts 4096
#define Dd 2560
#define Hh 10
#define BW 256
#define Mrows (Bb*Ts)   // 16384
#define NCHAN (Bb*Dd)   // 10240

// Scratch
__device__ float2 g_ax[(size_t)Bb * Ts * Dd];    // interleaved (a_eff, x_norm)
__device__ float  g_sp[Dd];                      // softplus(recurrent_param)
// Pre-packed, pre-swizzled fp16 tiles (exact smem layout, bulk-copied):
__device__ __align__(128) char g_aP[(size_t)Mrows * Dd * 2];
__device__ __align__(128) char g_wP[(size_t)Hh * 4 * 4 * 128 * 128];

// chunked-scan partials (chunk = 64 t's, matching the gates CTA tile)
#define CH 64
#define NCH (Ts / CH)    // 64
__device__ float g_P2[NCH * NCHAN];
__device__ float g_h2[NCH * NCHAN];
__device__ float g_H2[NCH * NCHAN];

// ---------------------------------------------------------------------------
__device__ __forceinline__ uint32_t smem_u32(const void* p) {
    uint32_t a;
    asm("{ .reg .u64 t; cvta.to.shared.u64 t, %1; cvt.u32.u64 %0, t; }" : "=r"(a) : "l"(p));
    return a;
}
__device__ __forceinline__ void mma_f16(float* c, const uint32_t* a,
                                        uint32_t b0, uint32_t b1) {
    asm volatile("mma.sync.aligned.m16n8k16.row.col.f32.f16.f16.f32 "
                 "{%0,%1,%2,%3}, {%4,%5,%6,%7}, {%8,%9}, {%0,%1,%2,%3};"
                 : "+f"(c[0]), "+f"(c[1]), "+f"(c[2]), "+f"(c[3])
                 : "r"(a[0]), "r"(a[1]), "r"(a[2]), "r"(a[3]), "r"(b0), "r"(b1));
}
__device__ __forceinline__ void ldm_x4(uint32_t* r, uint32_t addr) {
    asm volatile("ldmatrix.sync.aligned.m8n8.x4.shared.b16 {%0,%1,%2,%3}, [%4];"
                 : "=r"(r[0]), "=r"(r[1]), "=r"(r[2]), "=r"(r[3]) : "r"(addr));
}
#define MBAR_INIT(mbar, cnt) \
    asm volatile("mbarrier.init.shared.b64 [%0], %1;" :: "r"(mbar), "r"(cnt) : "memory")
#define MBAR_EXPECT(mbar, bytes) \
    asm volatile("mbarrier.arrive.expect_tx.shared.b64 _, [%0], %1;" :: "r"(mbar), "r"(bytes) : "memory")
#define MBAR_WAIT(mbar, par) do {                                              \
    uint32_t _m = (mbar), _p = (par), _d;                                      \
    asm volatile("{ .reg .pred p; mbarrier.try_wait.parity.acquire.cta.shared::cta.b64 p, [%1], %2; selp.b32 %0,1,0,p; }" \
                 : "=r"(_d) : "r"(_m), "r"(_p) : "memory");                    \
    if (!_d) {                                                                 \
        asm volatile("{ .reg .pred P1; WL_%=: mbarrier.try_wait.parity.acquire.cta.shared::cta.b64 P1, [%0], %1, 0x989680; @P1 bra.uni WD_%=; bra.uni WL_%=; WD_%=: }" \
                     :: "r"(_m), "r"(_p) : "memory");                          \
    } } while (0)
#define BULK_G2S(dst, src, sz, mbar) \
    asm volatile("cp.async.bulk.shared::cluster.global.mbarrier::complete_tx::bytes [%0], [%1], %2, [%3];" \
                 :: "r"(dst), "l"(src), "r"(sz), "r"(mbar) : "memory")

// ---------------------------------------------------------------------------
// Kernel 0: softplus table
// ---------------------------------------------------------------------------
__global__ void sp_kernel(const float* __restrict__ rp) {
    int d = blockIdx.x * blockDim.x + threadIdx.x;
    if (d < Dd) {
        float x = rp[d];
        g_sp[d] = (x > 20.0f) ? x : log1pf(__expf(x));
    }
}

// ---------------------------------------------------------------------------
// Kernel 0b: pack weights -> g_wP[h][nq][kt][n(128)][128B swizzled], fp16,
// interleaved n = 2*j_local + gate, j = nq*64 + j_local. One thread per 16B.
// ---------------------------------------------------------------------------
__global__ __launch_bounds__(256) void wt_kernel(
    const float* __restrict__ wig, const float* __restrict__ wrg)
{
    int idx = blockIdx.x * 256 + threadIdx.x;   // Hh*4*4*128*8 = 163840
    int ch = idx & 7;
    int n  = (idx >> 3) & 127;
    int kt = (idx >> 10) & 3;
    int nq = (idx >> 12) & 3;
    int h  = idx >> 14;
    int j  = nq * 64 + (n >> 1);
    const float* src = (n & 1) ? wrg : wig;
    src += (size_t)h * BW * BW + j;             // + k*BW
    int kb = kt * 64 + ch * 8;
    __half2 v[4];
    #pragma unroll
    for (int i = 0; i < 4; i++)
        v[i] = __floats2half2_rn(src[(size_t)(kb + 2*i) * BW],
                                 src[(size_t)(kb + 2*i + 1) * BW]);
    size_t dst = ((((size_t)(h * 4 + nq) * 4 + kt) * 128 + n) * 128) + ((ch ^ (n & 7)) * 16);
    *(uint4*)(g_wP + dst) = *(uint4*)v;
}

// ---------------------------------------------------------------------------
// Kernel 0c: pack activations -> g_aP[tile(64r)][h][kt][r(64)][128B swizzled].
// ---------------------------------------------------------------------------
__global__ __launch_bounds__(320) void cvt_kernel(const float* __restrict__ act) {
    int row = blockIdx.x;
    int k   = threadIdx.x * 8;
    int h   = k >> 8;
    int kk  = k & 255;
    int kt  = kk >> 6;
    int ch  = (kk >> 3) & 7;
    int r    = row & 63;
    int tile = row >> 6;
    const float* s = act + (size_t)row * Dd + k;
    float4 v0 = *(const float4*)s;
    float4 v1 = *(const float4*)(s + 4);
    __half2 hv[4];
    hv[0] = __floats2half2_rn(v0.x, v0.y);
    hv[1] = __floats2half2_rn(v0.z, v0.w);
    hv[2] = __floats2half2_rn(v1.x, v1.y);
    hv[3] = __floats2half2_rn(v1.z, v1.w);
    size_t dst = ((((size_t)(tile * Hh + h) * 4 + kt) * 64 + r) * 128) + ((ch ^ (r & 7)) * 16);
    *(uint4*)(g_aP + dst) = *(uint4*)hv;
}

// ---------------------------------------------------------------------------
// Kernel 1: fp16 mma gates GEMM (R13 — best measured). Epilogue: act from a
// bulk-copied fp16 A slab (kt=nq), scattered g_ax stores from regs, sm2
// staging only for fused chunk-scan aggregates -> g_P2/g_h2.
// Grid packing: blockIdx.x = tile*4 + nq (same-tile CTAs launch-adjacent
// for L2 reuse of the shared A slabs).
// ---------------------------------------------------------------------------
#define STG_A 8192
#define STG_W 16384
#define STG_B (STG_A + STG_W)          // 24576
#define SM_ST0 1024
#define SMEM_TOT (SM_ST0 + 2 * STG_B)  // 50176
#define EPI_PITCH 66                   // float2 pitch (2-way bank access)
#define SM_EPI (SM_ST0 + STG_A)        // 9216
#define SM_COMB (SM_EPI + 64 * EPI_PITCH * 8)   // 43008 ; +2048 <= 50176

__global__ __launch_bounds__(256, 4) void gates_mma_kernel(
    const int* __restrict__ pos,
    const float* __restrict__ big, const float* __restrict__ brg)
{
    extern __shared__ char smc[];
    const uint32_t sb = smem_u32(smc);

    const int tid = threadIdx.x;
    const int wid = tid >> 5, lane = tid & 31;
    const int g = lane >> 2, t = lane & 3;
    const int wm = wid & 1;
    const int wn = wid >> 1;
    const int h    = blockIdx.y;
    const int tile = blockIdx.x >> 2;
    const int nq   = blockIdx.x & 3;
    const int rb = tile * 64;

    if (tid == 0) { MBAR_INIT(sb + 0, 1); MBAR_INIT(sb + 8, 1); }
    __syncthreads();

    const char* aSrc = g_aP + ((size_t)(tile * Hh + h) * 4) * STG_A;
    const char* wSrc = g_wP + ((size_t)(h * 4 + nq) * 4) * STG_W;
    if (tid == 0) {
        #pragma unroll
        for (int s = 0; s < 2; s++) {
            uint32_t mb = sb + s * 8;
            uint32_t ds = sb + SM_ST0 + s * STG_B;
            MBAR_EXPECT(mb, STG_B);
            BULK_G2S(ds,         aSrc + (size_t)s * STG_A, STG_A, mb);
            BULK_G2S(ds + STG_A, wSrc + (size_t)s * STG_W, STG_W, mb);
        }
    }

    float acc[2][4][4];
    #pragma unroll
    for (int mt = 0; mt < 2; mt++)
        #pragma unroll
        for (int nt = 0; nt < 4; nt++)
            #pragma unroll
            for (int c = 0; c < 4; c++) acc[mt][nt][c] = 0.0f;

    const int jA    = lane & 7;
    const int hi16A = ((lane >> 4) & 1) << 4;
    const uint32_t rowA0 = (uint32_t)(wm * 32 + ((lane >> 3) & 1) * 8 + jA) * 128;
    const uint32_t rowB  = (uint32_t)(wn * 32 + (lane >> 3) * 8 + jA) * 128;

    #pragma unroll
    for (int kt = 0; kt < 4; kt++) {
        MBAR_WAIT(sb + (kt & 1) * 8, (kt >> 1) & 1);
        const uint32_t Abase = sb + SM_ST0 + (kt & 1) * STG_B;
        const uint32_t Wbase = Abase + STG_A;

        #pragma unroll
        for (int k16 = 0; k16 < 4; k16++) {
            const uint32_t b0 = (uint32_t)(((k16 * 2) ^ jA) << 4);
            uint32_t af0[4], af1[4], blo[4], bhi[4];
            ldm_x4(af0, Abase + rowA0 + (b0 ^ hi16A));
            ldm_x4(af1, Abase + rowA0 + 2048 + (b0 ^ hi16A));
            ldm_x4(blo, Wbase + rowB + b0);
            ldm_x4(bhi, Wbase + rowB + (b0 ^ 16));
            #pragma unroll
            for (int nt = 0; nt < 4; nt++) {
                mma_f16(acc[0][nt], af0, blo[nt], bhi[nt]);
                mma_f16(acc[1][nt], af1, blo[nt], bhi[nt]);
            }
        }
        if (kt < 2) {
            __syncthreads();
            if (tid == 0) {
                uint32_t mb = sb + (kt & 1) * 8;
                uint32_t ds = sb + SM_ST0 + (kt & 1) * STG_B;
                MBAR_EXPECT(mb, STG_B);
                BULK_G2S(ds,         aSrc + (size_t)(kt + 2) * STG_A, STG_A, mb);
                BULK_G2S(ds + STG_A, wSrc + (size_t)(kt + 2) * STG_W, STG_W, mb);
            }
        } else if (kt == 2) {
            // buffer0's A region is dead: DMA the epilogue act slab (kt=nq).
            __syncthreads();
            if (tid == 0) {
                MBAR_EXPECT(sb + 0, STG_A);
                BULK_G2S(sb + SM_ST0, aSrc + (size_t)nq * STG_A, STG_A, sb + 0);
            }
        }
    }

    __syncthreads();
    MBAR_WAIT(sb + 0, 0);          // epilogue act slab landed

    // -------- fused epilogue --------
    float bi[4], br[4], sp4[4];
    const int dg0 = h * BW + nq * 64 + wn * 16 + t;
    #pragma unroll
    for (int nt = 0; nt < 4; nt++) {
        int dg = dg0 + nt * 4;
        bi[nt]  = big[dg];
        br[nt]  = brg[dg];
        sp4[nt] = g_sp[dg];
    }

    float2* sm2 = (float2*)(smc + SM_EPI);   // [64 rows][pitch 66]
    const char* Ae = smc + SM_ST0;           // fp16 act slab (kt = nq), swizzled

    #pragma unroll
    for (int mt = 0; mt < 2; mt++) {
        int lr1 = wm * 32 + mt * 16 + g;
        int lr2 = lr1 + 8;
        int r1 = rb + lr1, r2 = rb + lr2;
        bool rs1 = (pos[r1] == 0);
        bool rs2 = (pos[r2] == 0);
        float2* o1 = g_ax + (size_t)r1 * Dd;
        float2* o2 = g_ax + (size_t)r2 * Dd;
        #pragma unroll
        for (int nt = 0; nt < 4; nt++) {
            int dg  = dg0 + nt * 4;
            int kk  = wn * 16 + nt * 4 + t;      // local channel == local k
            float av1 = __half2float(*(const __half*)(Ae + lr1 * 128 +
                            ((((kk >> 3) ^ (lr1 & 7)) << 4) | ((kk & 7) << 1))));
            float av2 = __half2float(*(const __half*)(Ae + lr2 * 128 +
                            ((((kk >> 3) ^ (lr2 & 7)) << 4) | ((kk & 7) << 1))));
            {
                float ig = 1.0f / (1.0f + __expf(-(acc[mt][nt][0] + bi[nt])));
                float rg = 1.0f / (1.0f + __expf(-(acc[mt][nt][1] + br[nt])));
                float a  = __expf(-8.0f * rg * sp4[nt]);
                float m  = sqrtf(fmaxf(fmaf(-a, a, 1.0f), 0.0f));
                float2 v = make_float2(rs1 ? 0.0f : a, av1 * ig * (rs1 ? 1.0f : m));
                o1[dg] = v;
                sm2[lr1 * EPI_PITCH + kk] = v;
            }
            {
                float ig = 1.0f / (1.0f + __expf(-(acc[mt][nt][2] + bi[nt])));
                float rg = 1.0f / (1.0f + __expf(-(acc[mt][nt][3] + br[nt])));
                float a  = __expf(-8.0f * rg * sp4[nt]);
                float m  = sqrtf(fmaxf(fmaf(-a, a, 1.0f), 0.0f));
                float2 v = make_float2(rs2 ? 0.0f : a, av2 * ig * (rs2 ? 1.0f : m));
                o2[dg] = v;
                sm2[lr2 * EPI_PITCH + kk] = v;
            }
        }
    }
    __syncthreads();

    // -------- fused chunk-scan aggregates (chunk = this tile's 64 t's) -----
    {
        int chl = tid & 63, seg = tid >> 6;      // 4 segments x 16 t
        float P = 1.0f, hh = 0.0f;
        #pragma unroll
        for (int i = 0; i < 16; i++) {
            float2 v = sm2[(seg * 16 + i) * EPI_PITCH + chl];
            P *= v.x;
            hh = fmaf(v.x, hh, v.y);
        }
        float2* comb = (float2*)(smc + SM_COMB);
        comb[seg * 64 + chl] = make_float2(P, hh);
        __syncthreads();
        if (tid < 64) {
            float Pt = 1.0f, ht = 0.0f;
            #pragma unroll
            for (int s = 0; s < 4; s++) {
                float2 v = comb[s * 64 + tid];
                ht = fmaf(v.x, ht, v.y);
                Pt *= v.x;
            }
            int bb = tile >> 6, cc = tile & 63;
            int chan = bb * Dd + h * BW + nq * 64 + tid;
            g_P2[cc * NCHAN + chan] = Pt;
            g_h2[cc * NCHAN + chan] = ht;
        }
    }
}

// ---------------------------------------------------------------------------
// Kernel 2b: cross-chunk recurrence (64 steps per channel)
// ---------------------------------------------------------------------------
__global__ __launch_bounds__(128) void scan_link_kernel() {
    int ch = blockIdx.x * 128 + threadIdx.x;
    float H = 0.0f;
    #pragma unroll
    for (int c = 0; c < NCH; c++) {
        g_H2[c * NCHAN + ch] = H;
        H = fmaf(g_P2[c * NCHAN + ch], H, g_h2[c * NCHAN + ch]);
    }
}

// ---------------------------------------------------------------------------
// Kernel 2c: seeded local scan, write output. 256-thr blocks, unroll 16,
// streaming loads. grid (40, 64).
// ---------------------------------------------------------------------------
__global__ __launch_bounds__(256) void scan_final_kernel(float* __restrict__ out) {
    int ch = blockIdx.x * 256 + threadIdx.x;
    int c  = blockIdx.y;
    int b  = ch / Dd;
    int d  = ch - b * Dd;
    size_t base = (size_t)b * Ts * Dd + (size_t)c * CH * Dd + d;

    float hacc = g_H2[c * NCHAN + ch];
    #pragma unroll 1
    for (int t0 = 0; t0 < CH; t0 += 16) {
        float2 v[16];
        #pragma unroll
        for (int u = 0; u < 16; u++)
            v[u] = __ldcs(&g_ax[base + (size_t)(t0 + u) * Dd]);
        #pragma unroll
        for (int u = 0; u < 16; u++) {
            hacc = fmaf(v[u].x, hacc, v[u].y);
            out[base + (size_t)(t0 + u) * Dd] = hacc;
        }
    }
}

// ---------------------------------------------------------------------------
extern "C" void kernel_launch(void* const* d_in, const int* in_sizes, int n_in,
                              void* d_out, int out_size) {
    const float* act = (const float*)d_in[0];
    const int*   pos = (const int*)  d_in[1];
    const float* wig = (const float*)d_in[2];
    const float* big = (const float*)d_in[3];
    const float* wrg = (const float*)d_in[4];
    const float* brg = (const float*)d_in[5];
    const float* rp  = (const float*)d_in[6];
    float* out = (float*)d_out;

    static int smem_set = 0;
    if (!smem_set) {
        cudaFuncSetAttribute(gates_mma_kernel,
                             cudaFuncAttributeMaxDynamicSharedMemorySize, SMEM_TOT);
        smem_set = 1;
    }

    sp_kernel<<<(Dd + 255) / 256, 256>>>(rp);
    wt_kernel<<<(Hh * 4 * 4 * 128 * 8) / 256, 256>>>(wig, wrg);
    cvt_kernel<<<Mrows, 320>>>(act);

    dim3 grid((Mrows / 64) * 4, Hh);   // (1024, 10): bx = tile*4 + nq
    gates_mma_kernel<<<grid, 256, SMEM_TOT>>>(pos, big, brg);

    scan_link_kernel<<<NCHAN / 128, 128>>>();
    dim3 sgrid(NCHAN / 256, NCH);      // (40, 64)
    scan_final_kernel<<<sgrid, 256>>>(out);
}

// round 16
// speedup vs baseline: 1.0830x; 1.0518x over previous
#include <cuda_runtime.h>
#include <cuda_fp16.h>
#include <cstdint>

// Problem constants (fixed by setup_inputs)
#define Bb 4
#define Ts 4096
#define Dd 2560
#define Hh 10
#define BW 256
#define Mrows (Bb*Ts)   // 16384
#define NCHAN (Bb*Dd)   // 10240

// Scratch
__device__ float2 g_ax[(size_t)Bb * Ts * Dd];    // interleaved (a_eff, x_norm)
__device__ float  g_sp[Dd];                      // softplus(recurrent_param)
// Pre-packed, pre-swizzled fp16 tiles (exact smem layout, bulk-copied):
__device__ __align__(128) char g_aP[(size_t)Mrows * Dd * 2];
__device__ __align__(128) char g_wP[(size_t)Hh * 4 * 4 * 128 * 128];

// chunked-scan partials (chunk = 64 t's, matching the gates CTA tile)
#define CH 64
#define NCH (Ts / CH)    // 64
__device__ float g_P2[NCH * NCHAN];
__device__ float g_h2[NCH * NCHAN];
__device__ float g_H2[NCH * NCHAN];

// ---------------------------------------------------------------------------
__device__ __forceinline__ uint32_t smem_u32(const void* p) {
    uint32_t a;
    asm("{ .reg .u64 t; cvta.to.shared.u64 t, %1; cvt.u32.u64 %0, t; }" : "=r"(a) : "l"(p));
    return a;
}
__device__ __forceinline__ float fast_sigmoid(float x) {
    float th;
    asm("tanh.approx.f32 %0, %1;" : "=f"(th) : "f"(x * 0.5f));
    return fmaf(th, 0.5f, 0.5f);
}
__device__ __forceinline__ void mma_f16(float* c, const uint32_t* a,
                                        uint32_t b0, uint32_t b1) {
    asm volatile("mma.sync.aligned.m16n8k16.row.col.f32.f16.f16.f32 "
                 "{%0,%1,%2,%3}, {%4,%5,%6,%7}, {%8,%9}, {%0,%1,%2,%3};"
                 : "+f"(c[0]), "+f"(c[1]), "+f"(c[2]), "+f"(c[3])
                 : "r"(a[0]), "r"(a[1]), "r"(a[2]), "r"(a[3]), "r"(b0), "r"(b1));
}
__device__ __forceinline__ void ldm_x4(uint32_t* r, uint32_t addr) {
    asm volatile("ldmatrix.sync.aligned.m8n8.x4.shared.b16 {%0,%1,%2,%3}, [%4];"
                 : "=r"(r[0]), "=r"(r[1]), "=r"(r[2]), "=r"(r[3]) : "r"(addr));
}
#define MBAR_INIT(mbar, cnt) \
    asm volatile("mbarrier.init.shared.b64 [%0], %1;" :: "r"(mbar), "r"(cnt) : "memory")
#define MBAR_EXPECT(mbar, bytes) \
    asm volatile("mbarrier.arrive.expect_tx.shared.b64 _, [%0], %1;" :: "r"(mbar), "r"(bytes) : "memory")
#define MBAR_WAIT(mbar, par) do {                                              \
    uint32_t _m = (mbar), _p = (par), _d;                                      \
    asm volatile("{ .reg .pred p; mbarrier.try_wait.parity.acquire.cta.shared::cta.b64 p, [%1], %2; selp.b32 %0,1,0,p; }" \
                 : "=r"(_d) : "r"(_m), "r"(_p) : "memory");                    \
    if (!_d) {                                                                 \
        asm volatile("{ .reg .pred P1; WL_%=: mbarrier.try_wait.parity.acquire.cta.shared::cta.b64 P1, [%0], %1, 0x989680; @P1 bra.uni WD_%=; bra.uni WL_%=; WD_%=: }" \
                     :: "r"(_m), "r"(_p) : "memory");                          \
    } } while (0)
#define BULK_G2S(dst, src, sz, mbar) \
    asm volatile("cp.async.bulk.shared::cluster.global.mbarrier::complete_tx::bytes [%0], [%1], %2, [%3];" \
                 :: "r"(dst), "l"(src), "r"(sz), "r"(mbar) : "memory")

// ---------------------------------------------------------------------------
// Kernel 0: softplus table
// ---------------------------------------------------------------------------
__global__ void sp_kernel(const float* __restrict__ rp) {
    int d = blockIdx.x * blockDim.x + threadIdx.x;
    if (d < Dd) {
        float x = rp[d];
        g_sp[d] = (x > 20.0f) ? x : log1pf(__expf(x));
    }
}

// ---------------------------------------------------------------------------
// Kernel 0b: pack weights -> g_wP[h][nq][kt][n(128)][128B swizzled], fp16,
// interleaved n = 2*j_local + gate, j = nq*64 + j_local. One thread per 16B.
// ---------------------------------------------------------------------------
__global__ __launch_bounds__(256) void wt_kernel(
    const float* __restrict__ wig, const float* __restrict__ wrg)
{
    int idx = blockIdx.x * 256 + threadIdx.x;   // Hh*4*4*128*8 = 163840
    int ch = idx & 7;
    int n  = (idx >> 3) & 127;
    int kt = (idx >> 10) & 3;
    int nq = (idx >> 12) & 3;
    int h  = idx >> 14;
    int j  = nq * 64 + (n >> 1);
    const float* src = (n & 1) ? wrg : wig;
    src += (size_t)h * BW * BW + j;             // + k*BW
    int kb = kt * 64 + ch * 8;
    __half2 v[4];
    #pragma unroll
    for (int i = 0; i < 4; i++)
        v[i] = __floats2half2_rn(src[(size_t)(kb + 2*i) * BW],
                                 src[(size_t)(kb + 2*i + 1) * BW]);
    size_t dst = ((((size_t)(h * 4 + nq) * 4 + kt) * 128 + n) * 128) + ((ch ^ (n & 7)) * 16);
    *(uint4*)(g_wP + dst) = *(uint4*)v;
}

// ---------------------------------------------------------------------------
// Kernel 0c: pack activations -> g_aP[tile(64r)][h][kt][r(64)][128B swizzled].
// ---------------------------------------------------------------------------
__global__ __launch_bounds__(320) void cvt_kernel(const float* __restrict__ act) {
    int row = blockIdx.x;
    int k   = threadIdx.x * 8;
    int h   = k >> 8;
    int kk  = k & 255;
    int kt  = kk >> 6;
    int ch  = (kk >> 3) & 7;
    int r    = row & 63;
    int tile = row >> 6;
    const float* s = act + (size_t)row * Dd + k;
    float4 v0 = *(const float4*)s;
    float4 v1 = *(const float4*)(s + 4);
    __half2 hv[4];
    hv[0] = __floats2half2_rn(v0.x, v0.y);
    hv[1] = __floats2half2_rn(v0.z, v0.w);
    hv[2] = __floats2half2_rn(v1.x, v1.y);
    hv[3] = __floats2half2_rn(v1.z, v1.w);
    size_t dst = ((((size_t)(tile * Hh + h) * 4 + kt) * 64 + r) * 128) + ((ch ^ (r & 7)) * 16);
    *(uint4*)(g_aP + dst) = *(uint4*)hv;
}

// ---------------------------------------------------------------------------
// Kernel 1: fp16 mma gates GEMM (R15 structure; epilogue sigmoids via
// tanh.approx to cut MUFU 6->4 per output).
// ---------------------------------------------------------------------------
#define STG_A 8192
#define STG_W 16384
#define STG_B (STG_A + STG_W)          // 24576
#define SM_ST0 1024
#define SMEM_TOT (SM_ST0 + 2 * STG_B)  // 50176
#define EPI_PITCH 66                   // float2 pitch (2-way bank access)
#define SM_EPI (SM_ST0 + STG_A)        // 9216
#define SM_COMB (SM_EPI + 64 * EPI_PITCH * 8)   // 43008 ; +2048 <= 50176

__global__ __launch_bounds__(256, 4) void gates_mma_kernel(
    const int* __restrict__ pos,
    const float* __restrict__ big, const float* __restrict__ brg)
{
    extern __shared__ char smc[];
    const uint32_t sb = smem_u32(smc);

    const int tid = threadIdx.x;
    const int wid = tid >> 5, lane = tid & 31;
    const int g = lane >> 2, t = lane & 3;
    const int wm = wid & 1;
    const int wn = wid >> 1;
    const int h    = blockIdx.y;
    const int tile = blockIdx.x >> 2;
    const int nq   = blockIdx.x & 3;
    const int rb = tile * 64;

    if (tid == 0) { MBAR_INIT(sb + 0, 1); MBAR_INIT(sb + 8, 1); }
    __syncthreads();

    const char* aSrc = g_aP + ((size_t)(tile * Hh + h) * 4) * STG_A;
    const char* wSrc = g_wP + ((size_t)(h * 4 + nq) * 4) * STG_W;
    if (tid == 0) {
        #pragma unroll
        for (int s = 0; s < 2; s++) {
            uint32_t mb = sb + s * 8;
            uint32_t ds = sb + SM_ST0 + s * STG_B;
            MBAR_EXPECT(mb, STG_B);
            BULK_G2S(ds,         aSrc + (size_t)s * STG_A, STG_A, mb);
            BULK_G2S(ds + STG_A, wSrc + (size_t)s * STG_W, STG_W, mb);
        }
    }

    float acc[2][4][4];
    #pragma unroll
    for (int mt = 0; mt < 2; mt++)
        #pragma unroll
        for (int nt = 0; nt < 4; nt++)
            #pragma unroll
            for (int c = 0; c < 4; c++) acc[mt][nt][c] = 0.0f;

    const int jA    = lane & 7;
    const int hi16A = ((lane >> 4) & 1) << 4;
    const uint32_t rowA0 = (uint32_t)(wm * 32 + ((lane >> 3) & 1) * 8 + jA) * 128;
    const uint32_t rowB  = (uint32_t)(wn * 32 + (lane >> 3) * 8 + jA) * 128;

    #pragma unroll
    for (int kt = 0; kt < 4; kt++) {
        MBAR_WAIT(sb + (kt & 1) * 8, (kt >> 1) & 1);
        const uint32_t Abase = sb + SM_ST0 + (kt & 1) * STG_B;
        const uint32_t Wbase = Abase + STG_A;

        #pragma unroll
        for (int k16 = 0; k16 < 4; k16++) {
            const uint32_t b0 = (uint32_t)(((k16 * 2) ^ jA) << 4);
            uint32_t af0[4], af1[4], blo[4], bhi[4];
            ldm_x4(af0, Abase + rowA0 + (b0 ^ hi16A));
            ldm_x4(af1, Abase + rowA0 + 2048 + (b0 ^ hi16A));
            ldm_x4(blo, Wbase + rowB + b0);
            ldm_x4(bhi, Wbase + rowB + (b0 ^ 16));
            #pragma unroll
            for (int nt = 0; nt < 4; nt++) {
                mma_f16(acc[0][nt], af0, blo[nt], bhi[nt]);
                mma_f16(acc[1][nt], af1, blo[nt], bhi[nt]);
            }
        }
        if (kt < 2) {
            __syncthreads();
            if (tid == 0) {
                uint32_t mb = sb + (kt & 1) * 8;
                uint32_t ds = sb + SM_ST0 + (kt & 1) * STG_B;
                MBAR_EXPECT(mb, STG_B);
                BULK_G2S(ds,         aSrc + (size_t)(kt + 2) * STG_A, STG_A, mb);
                BULK_G2S(ds + STG_A, wSrc + (size_t)(kt + 2) * STG_W, STG_W, mb);
            }
        } else if (kt == 2) {
            // buffer0's A region is dead: DMA the epilogue act slab (kt=nq).
            __syncthreads();
            if (tid == 0) {
                MBAR_EXPECT(sb + 0, STG_A);
                BULK_G2S(sb + SM_ST0, aSrc + (size_t)nq * STG_A, STG_A, sb + 0);
            }
        }
    }

    __syncthreads();
    MBAR_WAIT(sb + 0, 0);          // epilogue act slab landed

    // -------- fused epilogue --------
    float bi[4], br[4], sp4[4];
    const int dg0 = h * BW + nq * 64 + wn * 16 + t;
    #pragma unroll
    for (int nt = 0; nt < 4; nt++) {
        int dg = dg0 + nt * 4;
        bi[nt]  = big[dg];
        br[nt]  = brg[dg];
        sp4[nt] = g_sp[dg];
    }

    float2* sm2 = (float2*)(smc + SM_EPI);   // [64 rows][pitch 66]
    const char* Ae = smc + SM_ST0;           // fp16 act slab (kt = nq), swizzled

    #pragma unroll
    for (int mt = 0; mt < 2; mt++) {
        int lr1 = wm * 32 + mt * 16 + g;
        int lr2 = lr1 + 8;
        int r1 = rb + lr1, r2 = rb + lr2;
        bool rs1 = (pos[r1] == 0);
        bool rs2 = (pos[r2] == 0);
        float2* o1 = g_ax + (size_t)r1 * Dd;
        float2* o2 = g_ax + (size_t)r2 * Dd;
        #pragma unroll
        for (int nt = 0; nt < 4; nt++) {
            int dg  = dg0 + nt * 4;
            int kk  = wn * 16 + nt * 4 + t;      // local channel == local k
            float av1 = __half2float(*(const __half*)(Ae + lr1 * 128 +
                            ((((kk >> 3) ^ (lr1 & 7)) << 4) | ((kk & 7) << 1))));
            float av2 = __half2float(*(const __half*)(Ae + lr2 * 128 +
                            ((((kk >> 3) ^ (lr2 & 7)) << 4) | ((kk & 7) << 1))));
            {
                float ig = fast_sigmoid(acc[mt][nt][0] + bi[nt]);
                float rg = fast_sigmoid(acc[mt][nt][1] + br[nt]);
                float a  = __expf(-8.0f * rg * sp4[nt]);
                float m  = sqrtf(fmaxf(fmaf(-a, a, 1.0f), 0.0f));
                float2 v = make_float2(rs1 ? 0.0f : a, av1 * ig * (rs1 ? 1.0f : m));
                o1[dg] = v;
                sm2[lr1 * EPI_PITCH + kk] = v;
            }
            {
                float ig = fast_sigmoid(acc[mt][nt][2] + bi[nt]);
                float rg = fast_sigmoid(acc[mt][nt][3] + br[nt]);
                float a  = __expf(-8.0f * rg * sp4[nt]);
                float m  = sqrtf(fmaxf(fmaf(-a, a, 1.0f), 0.0f));
                float2 v = make_float2(rs2 ? 0.0f : a, av2 * ig * (rs2 ? 1.0f : m));
                o2[dg] = v;
                sm2[lr2 * EPI_PITCH + kk] = v;
            }
        }
    }
    __syncthreads();

    // -------- fused chunk-scan aggregates (chunk = this tile's 64 t's) -----
    {
        int chl = tid & 63, seg = tid >> 6;      // 4 segments x 16 t
        float P = 1.0f, hh = 0.0f;
        #pragma unroll
        for (int i = 0; i < 16; i++) {
            float2 v = sm2[(seg * 16 + i) * EPI_PITCH + chl];
            P *= v.x;
            hh = fmaf(v.x, hh, v.y);
        }
        float2* comb = (float2*)(smc + SM_COMB);
        comb[seg * 64 + chl] = make_float2(P, hh);
        __syncthreads();
        if (tid < 64) {
            float Pt = 1.0f, ht = 0.0f;
            #pragma unroll
            for (int s = 0; s < 4; s++) {
                float2 v = comb[s * 64 + tid];
                ht = fmaf(v.x, ht, v.y);
                Pt *= v.x;
            }
            int bb = tile >> 6, cc = tile & 63;
            int chan = bb * Dd + h * BW + nq * 64 + tid;
            g_P2[cc * NCHAN + chan] = Pt;
            g_h2[cc * NCHAN + chan] = ht;
        }
    }
}

// ---------------------------------------------------------------------------
// Kernel 2b: cross-chunk recurrence (64 steps per channel)
// ---------------------------------------------------------------------------
__global__ __launch_bounds__(128) void scan_link_kernel() {
    int ch = blockIdx.x * 128 + threadIdx.x;
    float H = 0.0f;
    #pragma unroll
    for (int c = 0; c < NCH; c++) {
        g_H2[c * NCHAN + ch] = H;
        H = fmaf(g_P2[c * NCHAN + ch], H, g_h2[c * NCHAN + ch]);
    }
}

// ---------------------------------------------------------------------------
// Kernel 2c: seeded local scan, write output. 256-thr blocks, unroll 16,
// streaming loads + streaming stores. grid (40, 64).
// ---------------------------------------------------------------------------
__global__ __launch_bounds__(256) void scan_final_kernel(float* __restrict__ out) {
    int ch = blockIdx.x * 256 + threadIdx.x;
    int c  = blockIdx.y;
    int b  = ch / Dd;
    int d  = ch - b * Dd;
    size_t base = (size_t)b * Ts * Dd + (size_t)c * CH * Dd + d;

    float hacc = g_H2[c * NCHAN + ch];
    #pragma unroll 1
    for (int t0 = 0; t0 < CH; t0 += 16) {
        float2 v[16];
        #pragma unroll
        for (int u = 0; u < 16; u++)
            v[u] = __ldcs(&g_ax[base + (size_t)(t0 + u) * Dd]);
        #pragma unroll
        for (int u = 0; u < 16; u++) {
            hacc = fmaf(v[u].x, hacc, v[u].y);
            __stcs(&out[base + (size_t)(t0 + u) * Dd], hacc);
        }
    }
}

// ---------------------------------------------------------------------------
extern "C" void kernel_launch(void* const* d_in, const int* in_sizes, int n_in,
                              void* d_out, int out_size) {
    const float* act = (const float*)d_in[0];
    const int*   pos = (const int*)  d_in[1];
    const float* wig = (const float*)d_in[2];
    const float* big = (const float*)d_in[3];
    const float* wrg = (const float*)d_in[4];
    const float* brg = (const float*)d_in[5];
    const float* rp  = (const float*)d_in[6];
    float* out = (float*)d_out;

    static int smem_set = 0;
    if (!smem_set) {
        cudaFuncSetAttribute(gates_mma_kernel,
                             cudaFuncAttributeMaxDynamicSharedMemorySize, SMEM_TOT);
        smem_set = 1;
    }

    sp_kernel<<<(Dd + 255) / 256, 256>>>(rp);
    wt_kernel<<<(Hh * 4 * 4 * 128 * 8) / 256, 256>>>(wig, wrg);
    cvt_kernel<<<Mrows, 320>>>(act);

    dim3 grid((Mrows / 64) * 4, Hh);   // (1024, 10): bx = tile*4 + nq
    gates_mma_kernel<<<grid, 256, SMEM_TOT>>>(pos, big, brg);

    scan_link_kernel<<<NCHAN / 128, 128>>>();
    dim3 sgrid(NCHAN / 256, NCH);      // (40, 64)
    scan_final_kernel<<<sgrid, 256>>>(out);
}

// round 17
// speedup vs baseline: 1.0977x; 1.0137x over previous
#include <cuda_runtime.h>
#include <cuda_fp16.h>
#include <cstdint>

// Problem constants (fixed by setup_inputs)
#define Bb 4
#define Ts 4096
#define Dd 2560
#define Hh 10
#define BW 256
#define Mrows (Bb*Ts)   // 16384
#define NCHAN (Bb*Dd)   // 10240

// Scratch
__device__ float2 g_ax[(size_t)Bb * Ts * Dd];    // interleaved (a_eff, x_norm)
__device__ float  g_sp[Dd];                      // softplus(recurrent_param)
// Pre-packed, pre-swizzled fp16 tiles (exact smem layout, bulk-copied):
__device__ __align__(128) char g_aP[(size_t)Mrows * Dd * 2];
__device__ __align__(128) char g_wP[(size_t)Hh * 4 * 4 * 128 * 128];

// chunked-scan partials (chunk = 64 t's, matching the gates CTA tile)
#define CH 64
#define NCH (Ts / CH)    // 64
__device__ float g_P2[NCH * NCHAN];
__device__ float g_h2[NCH * NCHAN];
__device__ float g_H2[NCH * NCHAN];

// ---------------------------------------------------------------------------
__device__ __forceinline__ uint32_t smem_u32(const void* p) {
    uint32_t a;
    asm("{ .reg .u64 t; cvta.to.shared.u64 t, %1; cvt.u32.u64 %0, t; }" : "=r"(a) : "l"(p));
    return a;
}
__device__ __forceinline__ float fast_sigmoid(float x) {
    float th;
    asm("tanh.approx.f32 %0, %1;" : "=f"(th) : "f"(x * 0.5f));
    return fmaf(th, 0.5f, 0.5f);
}
__device__ __forceinline__ void mma_f16(float* c, const uint32_t* a,
                                        uint32_t b0, uint32_t b1) {
    asm volatile("mma.sync.aligned.m16n8k16.row.col.f32.f16.f16.f32 "
                 "{%0,%1,%2,%3}, {%4,%5,%6,%7}, {%8,%9}, {%0,%1,%2,%3};"
                 : "+f"(c[0]), "+f"(c[1]), "+f"(c[2]), "+f"(c[3])
                 : "r"(a[0]), "r"(a[1]), "r"(a[2]), "r"(a[3]), "r"(b0), "r"(b1));
}
__device__ __forceinline__ void ldm_x4(uint32_t* r, uint32_t addr) {
    asm volatile("ldmatrix.sync.aligned.m8n8.x4.shared.b16 {%0,%1,%2,%3}, [%4];"
                 : "=r"(r[0]), "=r"(r[1]), "=r"(r[2]), "=r"(r[3]) : "r"(addr));
}
#define MBAR_INIT(mbar, cnt) \
    asm volatile("mbarrier.init.shared.b64 [%0], %1;" :: "r"(mbar), "r"(cnt) : "memory")
#define MBAR_EXPECT(mbar, bytes) \
    asm volatile("mbarrier.arrive.expect_tx.shared.b64 _, [%0], %1;" :: "r"(mbar), "r"(bytes) : "memory")
#define MBAR_WAIT(mbar, par) do {                                              \
    uint32_t _m = (mbar), _p = (par), _d;                                      \
    asm volatile("{ .reg .pred p; mbarrier.try_wait.parity.acquire.cta.shared::cta.b64 p, [%1], %2; selp.b32 %0,1,0,p; }" \
                 : "=r"(_d) : "r"(_m), "r"(_p) : "memory");                    \
    if (!_d) {                                                                 \
        asm volatile("{ .reg .pred P1; WL_%=: mbarrier.try_wait.parity.acquire.cta.shared::cta.b64 P1, [%0], %1, 0x989680; @P1 bra.uni WD_%=; bra.uni WL_%=; WD_%=: }" \
                     :: "r"(_m), "r"(_p) : "memory");                          \
    } } while (0)
#define BULK_G2S(dst, src, sz, mbar) \
    asm volatile("cp.async.bulk.shared::cluster.global.mbarrier::complete_tx::bytes [%0], [%1], %2, [%3];" \
                 :: "r"(dst), "l"(src), "r"(sz), "r"(mbar) : "memory")

// ---------------------------------------------------------------------------
// Kernel 0: softplus table
// ---------------------------------------------------------------------------
__global__ void sp_kernel(const float* __restrict__ rp) {
    int d = blockIdx.x * blockDim.x + threadIdx.x;
    if (d < Dd) {
        float x = rp[d];
        g_sp[d] = (x > 20.0f) ? x : log1pf(__expf(x));
    }
}

// ---------------------------------------------------------------------------
// Kernel 0b: pack weights -> g_wP[h][nq][kt][n(128)][128B swizzled], fp16,
// interleaved n = 2*j_local + gate, j = nq*64 + j_local. One thread per 16B.
// ---------------------------------------------------------------------------
__global__ __launch_bounds__(256) void wt_kernel(
    const float* __restrict__ wig, const float* __restrict__ wrg)
{
    int idx = blockIdx.x * 256 + threadIdx.x;   // Hh*4*4*128*8 = 163840
    int ch = idx & 7;
    int n  = (idx >> 3) & 127;
    int kt = (idx >> 10) & 3;
    int nq = (idx >> 12) & 3;
    int h  = idx >> 14;
    int j  = nq * 64 + (n >> 1);
    const float* src = (n & 1) ? wrg : wig;
    src += (size_t)h * BW * BW + j;             // + k*BW
    int kb = kt * 64 + ch * 8;
    __half2 v[4];
    #pragma unroll
    for (int i = 0; i < 4; i++)
        v[i] = __floats2half2_rn(src[(size_t)(kb + 2*i) * BW],
                                 src[(size_t)(kb + 2*i + 1) * BW]);
    size_t dst = ((((size_t)(h * 4 + nq) * 4 + kt) * 128 + n) * 128) + ((ch ^ (n & 7)) * 16);
    *(uint4*)(g_wP + dst) = *(uint4*)v;
}

// ---------------------------------------------------------------------------
// Kernel 0c: pack activations -> g_aP[tile(64r)][h][kt][r(64)][128B swizzled].
// ---------------------------------------------------------------------------
__global__ __launch_bounds__(320) void cvt_kernel(const float* __restrict__ act) {
    int row = blockIdx.x;
    int k   = threadIdx.x * 8;
    int h   = k >> 8;
    int kk  = k & 255;
    int kt  = kk >> 6;
    int ch  = (kk >> 3) & 7;
    int r    = row & 63;
    int tile = row >> 6;
    const float* s = act + (size_t)row * Dd + k;
    float4 v0 = *(const float4*)s;
    float4 v1 = *(const float4*)(s + 4);
    __half2 hv[4];
    hv[0] = __floats2half2_rn(v0.x, v0.y);
    hv[1] = __floats2half2_rn(v0.z, v0.w);
    hv[2] = __floats2half2_rn(v1.x, v1.y);
    hv[3] = __floats2half2_rn(v1.z, v1.w);
    size_t dst = ((((size_t)(tile * Hh + h) * 4 + kt) * 64 + r) * 128) + ((ch ^ (r & 7)) * 16);
    *(uint4*)(g_aP + dst) = *(uint4*)hv;
}

// ---------------------------------------------------------------------------
// Kernel 1: fp16 mma gates GEMM. tanh.approx sigmoids (R16) + coalesced g_ax
// stores from sm2 (R14 structure, re-applied now that L1 is the binder).
// ---------------------------------------------------------------------------
#define STG_A 8192
#define STG_W 16384
#define STG_B (STG_A + STG_W)          // 24576
#define SM_ST0 1024
#define SMEM_TOT (SM_ST0 + 2 * STG_B)  // 50176
#define EPI_PITCH 66                   // float2 pitch (2-way bank access)
#define SM_EPI (SM_ST0 + STG_A)        // 9216
#define SM_COMB (SM_EPI + 64 * EPI_PITCH * 8)   // 43008 ; +2048 <= 50176

__global__ __launch_bounds__(256, 4) void gates_mma_kernel(
    const int* __restrict__ pos,
    const float* __restrict__ big, const float* __restrict__ brg)
{
    extern __shared__ char smc[];
    const uint32_t sb = smem_u32(smc);

    const int tid = threadIdx.x;
    const int wid = tid >> 5, lane = tid & 31;
    const int g = lane >> 2, t = lane & 3;
    const int wm = wid & 1;
    const int wn = wid >> 1;
    const int h    = blockIdx.y;
    const int tile = blockIdx.x >> 2;
    const int nq   = blockIdx.x & 3;
    const int rb = tile * 64;

    if (tid == 0) { MBAR_INIT(sb + 0, 1); MBAR_INIT(sb + 8, 1); }
    __syncthreads();

    const char* aSrc = g_aP + ((size_t)(tile * Hh + h) * 4) * STG_A;
    const char* wSrc = g_wP + ((size_t)(h * 4 + nq) * 4) * STG_W;
    if (tid == 0) {
        #pragma unroll
        for (int s = 0; s < 2; s++) {
            uint32_t mb = sb + s * 8;
            uint32_t ds = sb + SM_ST0 + s * STG_B;
            MBAR_EXPECT(mb, STG_B);
            BULK_G2S(ds,         aSrc + (size_t)s * STG_A, STG_A, mb);
            BULK_G2S(ds + STG_A, wSrc + (size_t)s * STG_W, STG_W, mb);
        }
    }

    float acc[2][4][4];
    #pragma unroll
    for (int mt = 0; mt < 2; mt++)
        #pragma unroll
        for (int nt = 0; nt < 4; nt++)
            #pragma unroll
            for (int c = 0; c < 4; c++) acc[mt][nt][c] = 0.0f;

    const int jA    = lane & 7;
    const int hi16A = ((lane >> 4) & 1) << 4;
    const uint32_t rowA0 = (uint32_t)(wm * 32 + ((lane >> 3) & 1) * 8 + jA) * 128;
    const uint32_t rowB  = (uint32_t)(wn * 32 + (lane >> 3) * 8 + jA) * 128;

    #pragma unroll
    for (int kt = 0; kt < 4; kt++) {
        MBAR_WAIT(sb + (kt & 1) * 8, (kt >> 1) & 1);
        const uint32_t Abase = sb + SM_ST0 + (kt & 1) * STG_B;
        const uint32_t Wbase = Abase + STG_A;

        #pragma unroll
        for (int k16 = 0; k16 < 4; k16++) {
            const uint32_t b0 = (uint32_t)(((k16 * 2) ^ jA) << 4);
            uint32_t af0[4], af1[4], blo[4], bhi[4];
            ldm_x4(af0, Abase + rowA0 + (b0 ^ hi16A));
            ldm_x4(af1, Abase + rowA0 + 2048 + (b0 ^ hi16A));
            ldm_x4(blo, Wbase + rowB + b0);
            ldm_x4(bhi, Wbase + rowB + (b0 ^ 16));
            #pragma unroll
            for (int nt = 0; nt < 4; nt++) {
                mma_f16(acc[0][nt], af0, blo[nt], bhi[nt]);
                mma_f16(acc[1][nt], af1, blo[nt], bhi[nt]);
            }
        }
        if (kt < 2) {
            __syncthreads();
            if (tid == 0) {
                uint32_t mb = sb + (kt & 1) * 8;
                uint32_t ds = sb + SM_ST0 + (kt & 1) * STG_B;
                MBAR_EXPECT(mb, STG_B);
                BULK_G2S(ds,         aSrc + (size_t)(kt + 2) * STG_A, STG_A, mb);
                BULK_G2S(ds + STG_A, wSrc + (size_t)(kt + 2) * STG_W, STG_W, mb);
            }
        } else if (kt == 2) {
            // buffer0's A region is dead: DMA the epilogue act slab (kt=nq).
            __syncthreads();
            if (tid == 0) {
                MBAR_EXPECT(sb + 0, STG_A);
                BULK_G2S(sb + SM_ST0, aSrc + (size_t)nq * STG_A, STG_A, sb + 0);
            }
        }
    }

    __syncthreads();
    MBAR_WAIT(sb + 0, 0);          // epilogue act slab landed

    // -------- fused epilogue: gate math -> sm2 only --------
    float bi[4], br[4], sp4[4];
    const int dg0 = h * BW + nq * 64 + wn * 16 + t;
    #pragma unroll
    for (int nt = 0; nt < 4; nt++) {
        int dg = dg0 + nt * 4;
        bi[nt]  = big[dg];
        br[nt]  = brg[dg];
        sp4[nt] = g_sp[dg];
    }

    float2* sm2 = (float2*)(smc + SM_EPI);   // [64 rows][pitch 66]
    const char* Ae = smc + SM_ST0;           // fp16 act slab (kt = nq), swizzled

    #pragma unroll
    for (int mt = 0; mt < 2; mt++) {
        int lr1 = wm * 32 + mt * 16 + g;
        int lr2 = lr1 + 8;
        int r1 = rb + lr1, r2 = rb + lr2;
        bool rs1 = (pos[r1] == 0);
        bool rs2 = (pos[r2] == 0);
        #pragma unroll
        for (int nt = 0; nt < 4; nt++) {
            int kk  = wn * 16 + nt * 4 + t;      // local channel == local k
            float av1 = __half2float(*(const __half*)(Ae + lr1 * 128 +
                            ((((kk >> 3) ^ (lr1 & 7)) << 4) | ((kk & 7) << 1))));
            float av2 = __half2float(*(const __half*)(Ae + lr2 * 128 +
                            ((((kk >> 3) ^ (lr2 & 7)) << 4) | ((kk & 7) << 1))));
            {
                float ig = fast_sigmoid(acc[mt][nt][0] + bi[nt]);
                float rg = fast_sigmoid(acc[mt][nt][1] + br[nt]);
                float a  = __expf(-8.0f * rg * sp4[nt]);
                float m  = sqrtf(fmaxf(fmaf(-a, a, 1.0f), 0.0f));
                sm2[lr1 * EPI_PITCH + kk] =
                    make_float2(rs1 ? 0.0f : a, av1 * ig * (rs1 ? 1.0f : m));
            }
            {
                float ig = fast_sigmoid(acc[mt][nt][2] + bi[nt]);
                float rg = fast_sigmoid(acc[mt][nt][3] + br[nt]);
                float a  = __expf(-8.0f * rg * sp4[nt]);
                float m  = sqrtf(fmaxf(fmaf(-a, a, 1.0f), 0.0f));
                sm2[lr2 * EPI_PITCH + kk] =
                    make_float2(rs2 ? 0.0f : a, av2 * ig * (rs2 ? 1.0f : m));
            }
        }
    }
    __syncthreads();

    // -------- coalesced g_ax stores (warp = one 512B row) --------
    float2* gdst = g_ax + (size_t)rb * Dd + h * BW + nq * 64;
    #pragma unroll
    for (int i = 0; i < 8; i++) {
        int idx = i * 256 + tid;
        int r = idx >> 5, q = idx & 31;
        uint4 v = *(uint4*)&sm2[r * EPI_PITCH + q * 2];
        *(uint4*)(gdst + (size_t)r * Dd + q * 2) = v;
    }

    // -------- fused chunk-scan aggregates (chunk = this tile's 64 t's) -----
    {
        int chl = tid & 63, seg = tid >> 6;      // 4 segments x 16 t
        float P = 1.0f, hh = 0.0f;
        #pragma unroll
        for (int i = 0; i < 16; i++) {
            float2 v = sm2[(seg * 16 + i) * EPI_PITCH + chl];
            P *= v.x;
            hh = fmaf(v.x, hh, v.y);
        }
        float2* comb = (float2*)(smc + SM_COMB);
        comb[seg * 64 + chl] = make_float2(P, hh);
        __syncthreads();
        if (tid < 64) {
            float Pt = 1.0f, ht = 0.0f;
            #pragma unroll
            for (int s = 0; s < 4; s++) {
                float2 v = comb[s * 64 + tid];
                ht = fmaf(v.x, ht, v.y);
                Pt *= v.x;
            }
            int bb = tile >> 6, cc = tile & 63;
            int chan = bb * Dd + h * BW + nq * 64 + tid;
            g_P2[cc * NCHAN + chan] = Pt;
            g_h2[cc * NCHAN + chan] = ht;
        }
    }
}

// ---------------------------------------------------------------------------
// Kernel 2b: cross-chunk recurrence (64 steps per channel)
// ---------------------------------------------------------------------------
__global__ __launch_bounds__(128) void scan_link_kernel() {
    int ch = blockIdx.x * 128 + threadIdx.x;
    float H = 0.0f;
    #pragma unroll
    for (int c = 0; c < NCH; c++) {
        g_H2[c * NCHAN + ch] = H;
        H = fmaf(g_P2[c * NCHAN + ch], H, g_h2[c * NCHAN + ch]);
    }
}

// ---------------------------------------------------------------------------
// Kernel 2c: seeded local scan, write output. 256-thr blocks, unroll 16,
// streaming loads + streaming stores. grid (40, 64).
// ---------------------------------------------------------------------------
__global__ __launch_bounds__(256) void scan_final_kernel(float* __restrict__ out) {
    int ch = blockIdx.x * 256 + threadIdx.x;
    int c  = blockIdx.y;
    int b  = ch / Dd;
    int d  = ch - b * Dd;
    size_t base = (size_t)b * Ts * Dd + (size_t)c * CH * Dd + d;

    float hacc = g_H2[c * NCHAN + ch];
    #pragma unroll 1
    for (int t0 = 0; t0 < CH; t0 += 16) {
        float2 v[16];
        #pragma unroll
        for (int u = 0; u < 16; u++)
            v[u] = __ldcs(&g_ax[base + (size_t)(t0 + u) * Dd]);
        #pragma unroll
        for (int u = 0; u < 16; u++) {
            hacc = fmaf(v[u].x, hacc, v[u].y);
            __stcs(&out[base + (size_t)(t0 + u) * Dd], hacc);
        }
    }
}

// ---------------------------------------------------------------------------
extern "C" void kernel_launch(void* const* d_in, const int* in_sizes, int n_in,
                              void* d_out, int out_size) {
    const float* act = (const float*)d_in[0];
    const int*   pos = (const int*)  d_in[1];
    const float* wig = (const float*)d_in[2];
    const float* big = (const float*)d_in[3];
    const float* wrg = (const float*)d_in[4];
    const float* brg = (const float*)d_in[5];
    const float* rp  = (const float*)d_in[6];
    float* out = (float*)d_out;

    static int smem_set = 0;
    if (!smem_set) {
        cudaFuncSetAttribute(gates_mma_kernel,
                             cudaFuncAttributeMaxDynamicSharedMemorySize, SMEM_TOT);
        smem_set = 1;
    }

    sp_kernel<<<(Dd + 255) / 256, 256>>>(rp);
    wt_kernel<<<(Hh * 4 * 4 * 128 * 8) / 256, 256>>>(wig, wrg);
    cvt_kernel<<<Mrows, 320>>>(act);

    dim3 grid((Mrows / 64) * 4, Hh);   // (1024, 10): bx = tile*4 + nq
    gates_mma_kernel<<<grid, 256, SMEM_TOT>>>(pos, big, brg);

    scan_link_kernel<<<NCHAN / 128, 128>>>();
    dim3 sgrid(NCHAN / 256, NCH);      // (40, 64)
    scan_final_kernel<<<sgrid, 256>>>(out);
}